// round 2
// baseline (speedup 1.0000x reference)
#include <cuda_runtime.h>
#include <cstdint>

#define D_IN   128
#define D_OUT  128
#define NBASES 4
#define NCOLS  (NBASES * D_OUT)   // 512
#define N_MAX  100032

// Scratch: XW[n][b][o] = sum_i X[n][i] * w_bases[b][i][o], layout [N][4][128]
__device__ float g_XW[(size_t)N_MAX * NCOLS];

// ---------------- packed f32x2 helpers (PTX-only on sm_103a) ----------------
static __device__ __forceinline__ unsigned long long fma2(unsigned long long a,
                                                          unsigned long long b,
                                                          unsigned long long c) {
    unsigned long long d;
    asm("fma.rn.f32x2 %0, %1, %2, %3;" : "=l"(d) : "l"(a), "l"(b), "l"(c));
    return d;
}
static __device__ __forceinline__ unsigned long long dup2(float x) {
    unsigned long long d;
    asm("mov.b64 %0, {%1, %2};" : "=l"(d) : "f"(x), "f"(x));
    return d;
}
static __device__ __forceinline__ float2 unpack2(unsigned long long v) {
    float2 r;
    asm("mov.b64 {%0, %1}, %2;" : "=f"(r.x), "=f"(r.y) : "l"(v));
    return r;
}

// ---------------- Phase 1: XW = X @ w_bases (per base) ----------------
// Grid: (4 bases, ceil(N/64)). Block 256 threads.
// Tile: BM=64 rows x BN=128 cols, K chunked by 32.
// Thread tile: 8 rows x 4 cols, accumulators packed as f32x2 over row pairs.
#define BM 64
#define BK 32
#define XT_LD 66   // row stride for transposed X tile: 8B-aligned, 2-way-conflict stores

__global__ void __launch_bounds__(256)
gemm_xw_kernel(const float* __restrict__ X,
               const float* __restrict__ w_bases,
               int n_rows)
{
    __shared__ float Xt[BK][XT_LD];       // Xt[k][row]
    __shared__ float Ws[BK][D_OUT];       // Ws[k][col]

    const int b    = blockIdx.x;          // base 0..3 (fastest -> L2 reuse of X tile)
    const int row0 = blockIdx.y * BM;
    const float* W = w_bases + (size_t)b * D_IN * D_OUT;

    const int tid = threadIdx.x;
    const int tx  = tid & 31;             // col group: cols tx*4 .. tx*4+3
    const int ty  = tid >> 5;             // row group: rows ty*8 .. ty*8+7

    unsigned long long acc[4][4];         // [row-pair][col], each = 2 rows packed
    #pragma unroll
    for (int i = 0; i < 4; ++i)
        #pragma unroll
        for (int j = 0; j < 4; ++j) acc[i][j] = 0ull;

    for (int kc = 0; kc < D_IN; kc += BK) {
        // Load X tile (64 rows x 32 k), store transposed.
        {
            const int r  = tid >> 3;          // 0..31
            const int kk = (tid & 7) * 4;     // 0,4,...,28
            #pragma unroll
            for (int pass = 0; pass < 2; ++pass) {
                const int rr  = r + pass * 32;
                const int row = row0 + rr;
                float4 v = make_float4(0.f, 0.f, 0.f, 0.f);
                if (row < n_rows)
                    v = *reinterpret_cast<const float4*>(X + (size_t)row * D_IN + kc + kk);
                Xt[kk + 0][rr] = v.x;
                Xt[kk + 1][rr] = v.y;
                Xt[kk + 2][rr] = v.z;
                Xt[kk + 3][rr] = v.w;
            }
        }
        // Load W tile (32 k x 128 cols), coalesced float4.
        {
            const int col4 = (tid & 31) * 4;
            const int kr   = tid >> 5;        // 0..7
            #pragma unroll
            for (int pass = 0; pass < 4; ++pass) {
                const int k = kr + pass * 8;
                float4 v = *reinterpret_cast<const float4*>(W + (size_t)(kc + k) * D_OUT + col4);
                *reinterpret_cast<float4*>(&Ws[k][col4]) = v;
            }
        }
        __syncthreads();

        #pragma unroll 8
        for (int k = 0; k < BK; ++k) {
            const float* xr = &Xt[k][ty * 8];   // 8B-aligned (stride 66 floats)
            unsigned long long rp0 = *reinterpret_cast<const unsigned long long*>(xr + 0);
            unsigned long long rp1 = *reinterpret_cast<const unsigned long long*>(xr + 2);
            unsigned long long rp2 = *reinterpret_cast<const unsigned long long*>(xr + 4);
            unsigned long long rp3 = *reinterpret_cast<const unsigned long long*>(xr + 6);
            const float4 bv = *reinterpret_cast<const float4*>(&Ws[k][tx * 4]);
            const unsigned long long b0 = dup2(bv.x);
            const unsigned long long b1 = dup2(bv.y);
            const unsigned long long b2 = dup2(bv.z);
            const unsigned long long b3 = dup2(bv.w);

            acc[0][0] = fma2(rp0, b0, acc[0][0]);
            acc[0][1] = fma2(rp0, b1, acc[0][1]);
            acc[0][2] = fma2(rp0, b2, acc[0][2]);
            acc[0][3] = fma2(rp0, b3, acc[0][3]);
            acc[1][0] = fma2(rp1, b0, acc[1][0]);
            acc[1][1] = fma2(rp1, b1, acc[1][1]);
            acc[1][2] = fma2(rp1, b2, acc[1][2]);
            acc[1][3] = fma2(rp1, b3, acc[1][3]);
            acc[2][0] = fma2(rp2, b0, acc[2][0]);
            acc[2][1] = fma2(rp2, b1, acc[2][1]);
            acc[2][2] = fma2(rp2, b2, acc[2][2]);
            acc[2][3] = fma2(rp2, b3, acc[2][3]);
            acc[3][0] = fma2(rp3, b0, acc[3][0]);
            acc[3][1] = fma2(rp3, b1, acc[3][1]);
            acc[3][2] = fma2(rp3, b2, acc[3][2]);
            acc[3][3] = fma2(rp3, b3, acc[3][3]);
        }
        __syncthreads();
    }

    // Store: rows row0 + ty*8 + 2i(+1), col b*128 + tx*4 .. +3
    const size_t colbase = (size_t)b * D_OUT + tx * 4;
    #pragma unroll
    for (int i = 0; i < 4; ++i) {
        const float2 u0 = unpack2(acc[i][0]);
        const float2 u1 = unpack2(acc[i][1]);
        const float2 u2 = unpack2(acc[i][2]);
        const float2 u3 = unpack2(acc[i][3]);
        const int r_lo = row0 + ty * 8 + 2 * i;
        if (r_lo < n_rows) {
            float4 v = make_float4(u0.x, u1.x, u2.x, u3.x);
            *reinterpret_cast<float4*>(&g_XW[(size_t)r_lo * NCOLS + colbase]) = v;
        }
        if (r_lo + 1 < n_rows) {
            float4 v = make_float4(u0.y, u1.y, u2.y, u3.y);
            *reinterpret_cast<float4*>(&g_XW[(size_t)(r_lo + 1) * NCOLS + colbase]) = v;
        }
    }
}

// ---------------- Phase 2: zero output ----------------
__global__ void zero_kernel(float4* __restrict__ out, int n4)
{
    int i = blockIdx.x * blockDim.x + threadIdx.x;
    if (i < n4) out[i] = make_float4(0.f, 0.f, 0.f, 0.f);
}

// ---------------- Phase 3: edge scatter ----------------
// One warp per edge: gather XW[src] (4 bases x 128), combine with
// c_b = val * w_rel[rel][b], vector-reduce 512B into out[dst].
__global__ void __launch_bounds__(256)
scatter_kernel(const int*   __restrict__ esrc,
               const int*   __restrict__ edst,
               const int*   __restrict__ erel,
               const float* __restrict__ eval,
               const float* __restrict__ w_rel,
               float*       __restrict__ out,
               int E)
{
    const int e    = (blockIdx.x * 256 + threadIdx.x) >> 5;
    const int lane = threadIdx.x & 31;
    if (e >= E) return;

    const int   s = __ldg(esrc + e);
    const int   d = __ldg(edst + e);
    const int   r = __ldg(erel + e);
    const float v = __ldg(eval + e);

    const float c0 = v * __ldg(w_rel + r * NBASES + 0);
    const float c1 = v * __ldg(w_rel + r * NBASES + 1);
    const float c2 = v * __ldg(w_rel + r * NBASES + 2);
    const float c3 = v * __ldg(w_rel + r * NBASES + 3);

    const float4* p = reinterpret_cast<const float4*>(g_XW) + (size_t)s * (NCOLS / 4);
    const float4 a0 = __ldg(p + 0  + lane);
    const float4 a1 = __ldg(p + 32 + lane);
    const float4 a2 = __ldg(p + 64 + lane);
    const float4 a3 = __ldg(p + 96 + lane);

    float4 acc;
    acc.x = fmaf(c0, a0.x, fmaf(c1, a1.x, fmaf(c2, a2.x, c3 * a3.x)));
    acc.y = fmaf(c0, a0.y, fmaf(c1, a1.y, fmaf(c2, a2.y, c3 * a3.y)));
    acc.z = fmaf(c0, a0.z, fmaf(c1, a1.z, fmaf(c2, a2.z, c3 * a3.z)));
    acc.w = fmaf(c0, a0.w, fmaf(c1, a1.w, fmaf(c2, a2.w, c3 * a3.w)));

    float* q = out + (size_t)d * D_OUT + lane * 4;
    asm volatile("red.global.add.v4.f32 [%0], {%1, %2, %3, %4};"
                 :: "l"(q), "f"(acc.x), "f"(acc.y), "f"(acc.z), "f"(acc.w)
                 : "memory");
}

// ---------------- launch ----------------
extern "C" void kernel_launch(void* const* d_in, const int* in_sizes, int n_in,
                              void* d_out, int out_size)
{
    const float* X       = (const float*)d_in[0];
    const int*   esrc    = (const int*)  d_in[1];
    const int*   edst    = (const int*)  d_in[2];
    const int*   erel    = (const int*)  d_in[3];
    const float* eval    = (const float*)d_in[4];
    const float* w_bases = (const float*)d_in[5];
    const float* w_rel   = (const float*)d_in[6];
    float*       out     = (float*)d_out;

    const int n = in_sizes[0] / D_IN;   // 100000
    const int E = in_sizes[1];          // 640000

    // Phase 1: XW = X @ w_bases  (per-base column blocks; bases fastest for L2 X reuse)
    dim3 g1(NBASES, (n + BM - 1) / BM);
    gemm_xw_kernel<<<g1, 256>>>(X, w_bases, n);

    // Phase 2: zero output
    const int n4 = out_size / 4;
    zero_kernel<<<(n4 + 255) / 256, 256>>>((float4*)d_out, n4);

    // Phase 3: edge scatter (one warp per edge)
    scatter_kernel<<<(E + 7) / 8, 256>>>(esrc, edst, erel, eval, w_rel, out, E);
}

// round 5
// speedup vs baseline: 1.1930x; 1.1930x over previous
#include <cuda_runtime.h>
#include <cuda_bf16.h>
#include <cstdint>

#define D_IN   128
#define D_OUT  128
#define NBASES 4
#define NCOLS  512
#define N_MAX  100096   // multiple of 128

// Scratch
__device__ float g_XW[(size_t)N_MAX * NCOLS];   // [node][4*128] fp32

// Pre-transposed, hi/lo-split w_bases image, laid out exactly like the smem tile:
// Bt[n][k] with row stride 136 bf16 (272 B).
#define BT_STRIDE 136
#define BT_TILE   (128 * BT_STRIDE)
__device__ __nv_bfloat16 g_Bt[NBASES][2][BT_TILE];

// ======================= helpers =======================
static __device__ __forceinline__ uint32_t smem_u32(const void* p) {
    uint32_t a;
    asm("{ .reg .u64 t; cvta.to.shared.u64 t, %1; cvt.u32.u64 %0, t; }" : "=r"(a) : "l"(p));
    return a;
}

#define LDSM4(r, addr) \
    asm volatile("ldmatrix.sync.aligned.m8n8.x4.shared.b16 {%0,%1,%2,%3}, [%4];" \
        : "=r"((r)[0]), "=r"((r)[1]), "=r"((r)[2]), "=r"((r)[3]) : "r"(addr))

#define MMA_BF16(c, a, b0, b1) \
    asm volatile("mma.sync.aligned.m16n8k16.row.col.f32.bf16.bf16.f32 " \
        "{%0,%1,%2,%3}, {%4,%5,%6,%7}, {%8,%9}, {%0,%1,%2,%3};" \
        : "+f"((c)[0]), "+f"((c)[1]), "+f"((c)[2]), "+f"((c)[3]) \
        : "r"((a)[0]), "r"((a)[1]), "r"((a)[2]), "r"((a)[3]), "r"(b0), "r"(b1))

static __device__ __forceinline__ uint32_t pack_bf16(__nv_bfloat16 a, __nv_bfloat16 b) {
    return ((uint32_t)__bfloat16_as_ushort(b) << 16) | (uint32_t)__bfloat16_as_ushort(a);
}

// ======================= prep: split/transpose w_bases =======================
// w_bases layout: [b][k][n], n fastest. Build Bt[b][hi/lo][n*136 + k].
__global__ void prep_b_kernel(const float* __restrict__ w_bases) {
    const int id = blockIdx.x * 256 + threadIdx.x;   // 0..65535
    const int n = id & 127, k = (id >> 7) & 127, b = id >> 14;
    const float v = w_bases[id];
    const __nv_bfloat16 h = __float2bfloat16_rn(v);
    const __nv_bfloat16 l = __float2bfloat16_rn(v - __bfloat162float(h));
    g_Bt[b][0][n * BT_STRIDE + k] = h;
    g_Bt[b][1][n * BT_STRIDE + k] = l;
}

// ======================= Phase 1: mma.sync bf16 GEMM =======================
// CTA: 128 rows x 128 cols (one base). smem row stride 272 B (conflict-free ldmatrix).
#define AS_STRIDE 272
#define SM_A_HI 0
#define SM_A_LO 34816
#define SM_B_HI 69632
#define SM_B_LO 104448
#define SM_TOTAL 139264

__global__ void __launch_bounds__(256, 1)
gemm_mma_kernel(const float* __restrict__ X, int n_rows)
{
    extern __shared__ char smem[];
    const uint32_t sb = smem_u32(smem);
    const int tid = threadIdx.x, wid = tid >> 5, lane = tid & 31;
    const int base = blockIdx.x;          // 0..3, fastest -> L2 reuse of X tile
    const int m0 = blockIdx.y * 128;

    // ---- Load A tile: X[m0..m0+127][0..127] fp32 -> hi/lo bf16, swizzle-free padded rows.
    for (int s = tid; s < 4096; s += 256) {
        const int row = s >> 5, k4 = (s & 31) << 2;
        float4 v = make_float4(0.f, 0.f, 0.f, 0.f);
        const int gr = m0 + row;
        if (gr < n_rows) v = *reinterpret_cast<const float4*>(X + (size_t)gr * D_IN + k4);
        float vv[4] = {v.x, v.y, v.z, v.w};
        __nv_bfloat16 h[4], l[4];
        #pragma unroll
        for (int i = 0; i < 4; ++i) {
            h[i] = __float2bfloat16_rn(vv[i]);
            l[i] = __float2bfloat16_rn(vv[i] - __bfloat162float(h[i]));
        }
        const uint32_t off = (uint32_t)row * AS_STRIDE + k4 * 2;
        uint2 hv = make_uint2(pack_bf16(h[0], h[1]), pack_bf16(h[2], h[3]));
        uint2 lv = make_uint2(pack_bf16(l[0], l[1]), pack_bf16(l[2], l[3]));
        *reinterpret_cast<uint2*>(smem + SM_A_HI + off) = hv;
        *reinterpret_cast<uint2*>(smem + SM_A_LO + off) = lv;
    }
    // ---- Copy pre-built B tiles (hi+lo) linearly.
    {
        const uint4* srcH = reinterpret_cast<const uint4*>(g_Bt[base][0]);
        const uint4* srcL = reinterpret_cast<const uint4*>(g_Bt[base][1]);
        uint4* dH = reinterpret_cast<uint4*>(smem + SM_B_HI);
        uint4* dL = reinterpret_cast<uint4*>(smem + SM_B_LO);
        for (int i = tid; i < BT_TILE / 8; i += 256) { dH[i] = srcH[i]; dL[i] = srcL[i]; }
    }
    __syncthreads();

    // ---- Warp tiles: warp w -> rows (w&3)*32, cols (w>>2)*64.
    const int warp_m = (wid & 3) * 32;
    const int warp_n = (wid >> 2) * 64;

    float acc[2][8][4];
    #pragma unroll
    for (int mt = 0; mt < 2; ++mt)
        #pragma unroll
        for (int nt = 0; nt < 8; ++nt)
            #pragma unroll
            for (int i = 0; i < 4; ++i) acc[mt][nt][i] = 0.f;

    // ldmatrix per-lane address offsets (within a tile)
    const uint32_t a_off = (uint32_t)(warp_m + (lane & 15)) * AS_STRIDE + (lane >> 4) * 16;
    const uint32_t b_off = (uint32_t)(warp_n + ((lane >> 4) << 3) + (lane & 7)) * AS_STRIDE
                         + ((lane >> 3) & 1) * 16;

    for (int ks = 0; ks < 8; ++ks) {
        const uint32_t kb = (uint32_t)ks * 32;   // 16 bf16 = 32 B per k-step
        uint32_t ah[2][4], al[2][4], bh[4][4], bl[4][4];
        #pragma unroll
        for (int mt = 0; mt < 2; ++mt) {
            LDSM4(ah[mt], sb + SM_A_HI + a_off + (uint32_t)mt * 16 * AS_STRIDE + kb);
            LDSM4(al[mt], sb + SM_A_LO + a_off + (uint32_t)mt * 16 * AS_STRIDE + kb);
        }
        #pragma unroll
        for (int j = 0; j < 4; ++j) {
            LDSM4(bh[j], sb + SM_B_HI + b_off + (uint32_t)j * 16 * AS_STRIDE + kb);
            LDSM4(bl[j], sb + SM_B_LO + b_off + (uint32_t)j * 16 * AS_STRIDE + kb);
        }
        #pragma unroll
        for (int mt = 0; mt < 2; ++mt)
            #pragma unroll
            for (int nt = 0; nt < 8; ++nt) {
                const int j = nt >> 1, s2 = (nt & 1) * 2;
                MMA_BF16(acc[mt][nt], ah[mt], bh[j][s2], bh[j][s2 + 1]);  // hi*hi
                MMA_BF16(acc[mt][nt], al[mt], bh[j][s2], bh[j][s2 + 1]);  // lo*hi
                MMA_BF16(acc[mt][nt], ah[mt], bl[j][s2], bl[j][s2 + 1]);  // hi*lo
            }
    }

    // ---- Epilogue: write fp32 to g_XW.
    const int r_base = m0 + warp_m + (lane >> 2);
    #pragma unroll
    for (int mt = 0; mt < 2; ++mt) {
        const int row0 = r_base + mt * 16;
        #pragma unroll
        for (int nt = 0; nt < 8; ++nt) {
            const int col = base * 128 + warp_n + nt * 8 + (lane & 3) * 2;
            if (row0 < n_rows) {
                float2 v = make_float2(acc[mt][nt][0], acc[mt][nt][1]);
                *reinterpret_cast<float2*>(g_XW + (size_t)row0 * NCOLS + col) = v;
            }
            if (row0 + 8 < n_rows) {
                float2 v = make_float2(acc[mt][nt][2], acc[mt][nt][3]);
                *reinterpret_cast<float2*>(g_XW + (size_t)(row0 + 8) * NCOLS + col) = v;
            }
        }
    }
}

// ======================= Phase 2: zero output =======================
__global__ void zero_kernel(float4* __restrict__ out, int n4) {
    int i = blockIdx.x * blockDim.x + threadIdx.x;
    if (i < n4) out[i] = make_float4(0.f, 0.f, 0.f, 0.f);
}

// ======================= Phase 3: edge scatter =======================
__global__ void __launch_bounds__(256)
scatter_kernel(const int*   __restrict__ esrc,
               const int*   __restrict__ edst,
               const int*   __restrict__ erel,
               const float* __restrict__ eval,
               const float* __restrict__ w_rel,
               float*       __restrict__ out,
               int E)
{
    const int e    = (blockIdx.x * 256 + threadIdx.x) >> 5;
    const int lane = threadIdx.x & 31;
    if (e >= E) return;

    const int   s = __ldg(esrc + e);
    const int   d = __ldg(edst + e);
    const int   r = __ldg(erel + e);
    const float v = __ldg(eval + e);

    const float c0 = v * __ldg(w_rel + r * NBASES + 0);
    const float c1 = v * __ldg(w_rel + r * NBASES + 1);
    const float c2 = v * __ldg(w_rel + r * NBASES + 2);
    const float c3 = v * __ldg(w_rel + r * NBASES + 3);

    const float4* p = reinterpret_cast<const float4*>(g_XW) + (size_t)s * (NCOLS / 4);
    const float4 a0 = __ldg(p + 0  + lane);
    const float4 a1 = __ldg(p + 32 + lane);
    const float4 a2 = __ldg(p + 64 + lane);
    const float4 a3 = __ldg(p + 96 + lane);

    float4 acc;
    acc.x = fmaf(c0, a0.x, fmaf(c1, a1.x, fmaf(c2, a2.x, c3 * a3.x)));
    acc.y = fmaf(c0, a0.y, fmaf(c1, a1.y, fmaf(c2, a2.y, c3 * a3.y)));
    acc.z = fmaf(c0, a0.z, fmaf(c1, a1.z, fmaf(c2, a2.z, c3 * a3.z)));
    acc.w = fmaf(c0, a0.w, fmaf(c1, a1.w, fmaf(c2, a2.w, c3 * a3.w)));

    float* q = out + (size_t)d * D_OUT + lane * 4;
    asm volatile("red.global.add.v4.f32 [%0], {%1, %2, %3, %4};"
                 :: "l"(q), "f"(acc.x), "f"(acc.y), "f"(acc.z), "f"(acc.w)
                 : "memory");
}

// ======================= launch =======================
extern "C" void kernel_launch(void* const* d_in, const int* in_sizes, int n_in,
                              void* d_out, int out_size)
{
    const float* X       = (const float*)d_in[0];
    const int*   esrc    = (const int*)  d_in[1];
    const int*   edst    = (const int*)  d_in[2];
    const int*   erel    = (const int*)  d_in[3];
    const float* eval    = (const float*)d_in[4];
    const float* w_bases = (const float*)d_in[5];
    const float* w_rel   = (const float*)d_in[6];
    float*       out     = (float*)d_out;

    const int n = in_sizes[0] / D_IN;   // 100000
    const int E = in_sizes[1];          // 640000

    cudaFuncSetAttribute(gemm_mma_kernel, cudaFuncAttributeMaxDynamicSharedMemorySize, SM_TOTAL);

    // Prep: transpose + hi/lo split of w_bases into smem-image layout.
    prep_b_kernel<<<256, 256>>>(w_bases);

    // Phase 1: XW = X @ w_bases via mma.sync bf16 (3-pass split)
    dim3 g1(NBASES, (n + 127) / 128);
    gemm_mma_kernel<<<g1, 256, SM_TOTAL>>>(X, n);

    // Phase 2: zero output
    const int n4 = out_size / 4;
    zero_kernel<<<(n4 + 255) / 256, 256>>>((float4*)d_out, n4);

    // Phase 3: edge scatter (one warp per edge)
    scatter_kernel<<<(E + 7) / 8, 256>>>(esrc, edst, erel, eval, w_rel, out, E);
}

// round 6
// speedup vs baseline: 2.3642x; 1.9817x over previous
#include <cuda_runtime.h>
#include <cuda_fp16.h>
#include <cstdint>

#define D_IN   128
#define D_OUT  128
#define NBASES 4
#define NCOLS  512
#define N_MAX  100096          // multiple of 256
#define NBLK   (N_MAX / 256)   // 391
#define E_MAX  655360

// ---------------- scratch ----------------
__device__ float g_XW[(size_t)N_MAX * NCOLS];                 // [node][512] fp32
__device__ __align__(16) __half g_Xh[(size_t)N_MAX * D_IN];   // fp16 hi
__device__ __align__(16) __half g_Xl[(size_t)N_MAX * D_IN];   // fp16 lo
#define BT_STRIDE 136
__device__ __align__(16) __half g_Bt[NBASES][128 * BT_STRIDE];
// sort scratch
__device__ int    g_hist[N_MAX];
__device__ int    g_rowptr[N_MAX + 1];
__device__ int    g_cursor[N_MAX];
__device__ int    g_bsum[NBLK];
__device__ int    g_dst_s[E_MAX];
__device__ float4 g_c_s[E_MAX];

// ---------------- helpers ----------------
static __device__ __forceinline__ uint32_t smem_u32(const void* p) {
    uint32_t a;
    asm("{ .reg .u64 t; cvta.to.shared.u64 t, %1; cvt.u32.u64 %0, t; }" : "=r"(a) : "l"(p));
    return a;
}
#define LDSM4(r, addr) \
    asm volatile("ldmatrix.sync.aligned.m8n8.x4.shared.b16 {%0,%1,%2,%3}, [%4];" \
        : "=r"((r)[0]), "=r"((r)[1]), "=r"((r)[2]), "=r"((r)[3]) : "r"(addr))
#define MMA_F16(c, a, b0, b1) \
    asm volatile("mma.sync.aligned.m16n8k16.row.col.f32.f16.f16.f32 " \
        "{%0,%1,%2,%3}, {%4,%5,%6,%7}, {%8,%9}, {%0,%1,%2,%3};" \
        : "+f"((c)[0]), "+f"((c)[1]), "+f"((c)[2]), "+f"((c)[3]) \
        : "r"((a)[0]), "r"((a)[1]), "r"((a)[2]), "r"((a)[3]), "r"(b0), "r"(b1))

static __device__ __forceinline__ uint32_t packh(__half a, __half b) {
    return ((uint32_t)__half_as_ushort(b) << 16) | (uint32_t)__half_as_ushort(a);
}

// ---------------- prep: X -> fp16 hi/lo ----------------
__global__ void convert_x_kernel(const float* __restrict__ X, int total4) {
    int i = blockIdx.x * blockDim.x + threadIdx.x;
    if (i >= total4) return;
    float4 v = reinterpret_cast<const float4*>(X)[i];
    float vv[4] = {v.x, v.y, v.z, v.w};
    __half h[4], l[4];
    #pragma unroll
    for (int j = 0; j < 4; ++j) {
        h[j] = __float2half_rn(vv[j]);
        l[j] = __float2half_rn(vv[j] - __half2float(h[j]));
    }
    reinterpret_cast<uint2*>(g_Xh)[i] = make_uint2(packh(h[0], h[1]), packh(h[2], h[3]));
    reinterpret_cast<uint2*>(g_Xl)[i] = make_uint2(packh(l[0], l[1]), packh(l[2], l[3]));
}

// ---------------- prep: w_bases -> transposed fp16 smem image ----------------
__global__ void prep_b_kernel(const float* __restrict__ w_bases) {
    const int id = blockIdx.x * 256 + threadIdx.x;   // 0..65535
    const int n = id & 127, k = (id >> 7) & 127, b = id >> 14;
    g_Bt[b][n * BT_STRIDE + k] = __float2half_rn(w_bases[id]);
}

// ---------------- Phase 1: fp16 2-pass mma.sync GEMM ----------------
#define AS_STRIDE 272
#define SM_A_HI 0
#define SM_A_LO 34816
#define SM_B    69632
#define SM_TOTAL 104448

__global__ void __launch_bounds__(256, 2)
gemm_mma_kernel(int n_rows)
{
    extern __shared__ char smem[];
    const uint32_t sb = smem_u32(smem);
    const int tid = threadIdx.x, wid = tid >> 5, lane = tid & 31;
    const int base = blockIdx.x;
    const int m0 = blockIdx.y * 128;

    // A hi/lo: linear copy (rows of 256B) into 272B-stride smem rows.
    for (int i = tid; i < 2048; i += 256) {
        const int row = i >> 4, seg = (i & 15) * 16;
        const size_t gsrc = (size_t)(m0 + row) * 256 + seg;
        uint4 hv = *reinterpret_cast<const uint4*>(reinterpret_cast<const char*>(g_Xh) + gsrc);
        uint4 lv = *reinterpret_cast<const uint4*>(reinterpret_cast<const char*>(g_Xl) + gsrc);
        *reinterpret_cast<uint4*>(smem + SM_A_HI + row * AS_STRIDE + seg) = hv;
        *reinterpret_cast<uint4*>(smem + SM_A_LO + row * AS_STRIDE + seg) = lv;
    }
    // B: straight 34816B copy (pre-built image already has 272B row stride).
    {
        const uint4* src = reinterpret_cast<const uint4*>(g_Bt[base]);
        uint4* dst = reinterpret_cast<uint4*>(smem + SM_B);
        for (int i = tid; i < 2176; i += 256) dst[i] = src[i];
    }
    __syncthreads();

    const int warp_m = (wid & 3) * 32;
    const int warp_n = (wid >> 2) * 64;

    float acc[2][8][4];
    #pragma unroll
    for (int mt = 0; mt < 2; ++mt)
        #pragma unroll
        for (int nt = 0; nt < 8; ++nt)
            #pragma unroll
            for (int i = 0; i < 4; ++i) acc[mt][nt][i] = 0.f;

    const uint32_t a_off = (uint32_t)(warp_m + (lane & 15)) * AS_STRIDE + (lane >> 4) * 16;
    const uint32_t b_off = (uint32_t)(warp_n + ((lane >> 4) << 3) + (lane & 7)) * AS_STRIDE
                         + ((lane >> 3) & 1) * 16;

    #pragma unroll
    for (int ks = 0; ks < 8; ++ks) {
        const uint32_t kb = (uint32_t)ks * 32;
        uint32_t ah[2][4], al[2][4];
        #pragma unroll
        for (int mt = 0; mt < 2; ++mt) {
            LDSM4(ah[mt], sb + SM_A_HI + a_off + (uint32_t)mt * 16 * AS_STRIDE + kb);
            LDSM4(al[mt], sb + SM_A_LO + a_off + (uint32_t)mt * 16 * AS_STRIDE + kb);
        }
        #pragma unroll
        for (int j = 0; j < 4; ++j) {
            uint32_t b[4];
            LDSM4(b, sb + SM_B + b_off + (uint32_t)j * 16 * AS_STRIDE + kb);
            #pragma unroll
            for (int mt = 0; mt < 2; ++mt) {
                MMA_F16(acc[mt][2 * j + 0], ah[mt], b[0], b[1]);
                MMA_F16(acc[mt][2 * j + 1], ah[mt], b[2], b[3]);
                MMA_F16(acc[mt][2 * j + 0], al[mt], b[0], b[1]);
                MMA_F16(acc[mt][2 * j + 1], al[mt], b[2], b[3]);
            }
        }
    }

    // epilogue (rows < N_MAX always in-bounds; rows >= n_rows are never consumed)
    const int r_base = m0 + warp_m + (lane >> 2);
    #pragma unroll
    for (int mt = 0; mt < 2; ++mt) {
        const int row0 = r_base + mt * 16;
        #pragma unroll
        for (int nt = 0; nt < 8; ++nt) {
            const int col = base * 128 + warp_n + nt * 8 + (lane & 3) * 2;
            *reinterpret_cast<float2*>(g_XW + (size_t)row0 * NCOLS + col) =
                make_float2(acc[mt][nt][0], acc[mt][nt][1]);
            *reinterpret_cast<float2*>(g_XW + (size_t)(row0 + 8) * NCOLS + col) =
                make_float2(acc[mt][nt][2], acc[mt][nt][3]);
        }
    }
}

// ---------------- counting sort by src ----------------
__global__ void zero_hist_kernel() {
    int i = blockIdx.x * 256 + threadIdx.x;
    if (i < N_MAX) g_hist[i] = 0;
}
__global__ void hist_kernel(const int* __restrict__ esrc, int E) {
    int e = blockIdx.x * 256 + threadIdx.x;
    if (e < E) atomicAdd(&g_hist[esrc[e]], 1);
}
// block-level exclusive scan of hist -> g_rowptr (partial), block totals -> g_bsum
__global__ void scan1_kernel() {
    __shared__ int s_w[8];
    const int t = threadIdx.x, w = t >> 5, lane = t & 31;
    const int i = blockIdx.x * 256 + t;
    const int x = g_hist[i];
    int v = x;
    #pragma unroll
    for (int o = 1; o < 32; o <<= 1) {
        int y = __shfl_up_sync(0xFFFFFFFF, v, o);
        if (lane >= o) v += y;
    }
    if (lane == 31) s_w[w] = v;
    __syncthreads();
    if (t < 8) {
        int sv = s_w[t];
        #pragma unroll
        for (int o = 1; o < 8; o <<= 1) {
            int y = __shfl_up_sync(0xFF, sv, o);
            if (t >= o) sv += y;
        }
        s_w[t] = sv;
    }
    __syncthreads();
    const int off = (w > 0) ? s_w[w - 1] : 0;
    g_rowptr[i] = off + v - x;            // block-local exclusive prefix
    if (t == 0) g_bsum[blockIdx.x] = s_w[7];
}
__global__ void scan2_kernel() {
    __shared__ int sm[512];
    const int t = threadIdx.x;
    const int v = (t < NBLK) ? g_bsum[t] : 0;
    sm[t] = v;
    __syncthreads();
    for (int o = 1; o < 512; o <<= 1) {
        int y = (t >= o) ? sm[t - o] : 0;
        __syncthreads();
        sm[t] += y;
        __syncthreads();
    }
    if (t < NBLK) g_bsum[t] = sm[t] - v;  // exclusive
}
__global__ void scan3_kernel(int E) {
    const int i = blockIdx.x * 256 + threadIdx.x;
    if (i < N_MAX) {
        const int r = g_rowptr[i] + g_bsum[i >> 8];
        g_rowptr[i] = r;
        g_cursor[i] = r;
    }
    if (i == 0) g_rowptr[N_MAX] = E;
}
__global__ void perm_kernel(const int* __restrict__ esrc, const int* __restrict__ edst,
                            const int* __restrict__ erel, const float* __restrict__ eval,
                            const float* __restrict__ w_rel, int E) {
    const int e = blockIdx.x * 256 + threadIdx.x;
    if (e >= E) return;
    const int s = esrc[e];
    const int pos = atomicAdd(&g_cursor[s], 1);
    g_dst_s[pos] = edst[e];
    const int r = erel[e];
    const float v = eval[e];
    float4 c;
    c.x = v * __ldg(w_rel + r * NBASES + 0);
    c.y = v * __ldg(w_rel + r * NBASES + 1);
    c.z = v * __ldg(w_rel + r * NBASES + 2);
    c.w = v * __ldg(w_rel + r * NBASES + 3);
    g_c_s[pos] = c;
}

// ---------------- Phase 2: zero output ----------------
__global__ void zero_kernel(float4* __restrict__ out, int n4) {
    int i = blockIdx.x * blockDim.x + threadIdx.x;
    if (i < n4) out[i] = make_float4(0.f, 0.f, 0.f, 0.f);
}

// ---------------- Phase 3: warp-per-src scatter ----------------
__global__ void __launch_bounds__(256)
scatter_kernel(float* __restrict__ out)
{
    const int src  = (blockIdx.x * 256 + threadIdx.x) >> 5;
    const int lane = threadIdx.x & 31;
    if (src >= N_MAX) return;
    const int beg = __ldg(g_rowptr + src);
    const int end = __ldg(g_rowptr + src + 1);
    if (beg >= end) return;

    const float4* p = reinterpret_cast<const float4*>(g_XW) + (size_t)src * (NCOLS / 4) + lane;
    const float4 a0 = __ldg(p + 0);
    const float4 a1 = __ldg(p + 32);
    const float4 a2 = __ldg(p + 64);
    const float4 a3 = __ldg(p + 96);

    for (int j = beg; j < end; ++j) {
        const float4 c = __ldg(g_c_s + j);
        const int d = __ldg(g_dst_s + j);
        float4 acc;
        acc.x = fmaf(c.x, a0.x, fmaf(c.y, a1.x, fmaf(c.z, a2.x, c.w * a3.x)));
        acc.y = fmaf(c.x, a0.y, fmaf(c.y, a1.y, fmaf(c.z, a2.y, c.w * a3.y)));
        acc.z = fmaf(c.x, a0.z, fmaf(c.y, a1.z, fmaf(c.z, a2.z, c.w * a3.z)));
        acc.w = fmaf(c.x, a0.w, fmaf(c.y, a1.w, fmaf(c.z, a2.w, c.w * a3.w)));
        float* q = out + (size_t)d * D_OUT + lane * 4;
        asm volatile("red.global.add.v4.f32 [%0], {%1, %2, %3, %4};"
                     :: "l"(q), "f"(acc.x), "f"(acc.y), "f"(acc.z), "f"(acc.w)
                     : "memory");
    }
}

// ---------------- launch ----------------
extern "C" void kernel_launch(void* const* d_in, const int* in_sizes, int n_in,
                              void* d_out, int out_size)
{
    const float* X       = (const float*)d_in[0];
    const int*   esrc    = (const int*)  d_in[1];
    const int*   edst    = (const int*)  d_in[2];
    const int*   erel    = (const int*)  d_in[3];
    const float* eval    = (const float*)d_in[4];
    const float* w_bases = (const float*)d_in[5];
    const float* w_rel   = (const float*)d_in[6];
    float*       out     = (float*)d_out;

    const int n = in_sizes[0] / D_IN;   // 100000
    const int E = in_sizes[1];          // 640000

    cudaFuncSetAttribute(gemm_mma_kernel, cudaFuncAttributeMaxDynamicSharedMemorySize, SM_TOTAL);

    // sort pipeline (independent of GEMM inputs, runs first)
    zero_hist_kernel<<<NBLK, 256>>>();
    hist_kernel<<<(E + 255) / 256, 256>>>(esrc, E);
    scan1_kernel<<<NBLK, 256>>>();
    scan2_kernel<<<1, 512>>>();
    scan3_kernel<<<NBLK, 256>>>(E);
    perm_kernel<<<(E + 255) / 256, 256>>>(esrc, edst, erel, eval, w_rel, E);

    // GEMM prep + GEMM
    const int total4 = n * D_IN / 4;
    convert_x_kernel<<<(total4 + 255) / 256, 256>>>(X, total4);
    prep_b_kernel<<<256, 256>>>(w_bases);
    dim3 g1(NBASES, (n + 127) / 128);
    gemm_mma_kernel<<<g1, 256, SM_TOTAL>>>(n);

    // zero + scatter
    const int n4 = out_size / 4;
    zero_kernel<<<(n4 + 255) / 256, 256>>>((float4*)d_out, n4);
    scatter_kernel<<<N_MAX / 8, 256>>>(out);
}

// round 7
// speedup vs baseline: 3.0131x; 1.2744x over previous
#include <cuda_runtime.h>
#include <cuda_fp16.h>
#include <cstdint>

#define D_IN   128
#define D_OUT  128
#define NBASES 4
#define NCOLS  512
#define N_MAX  100096          // multiple of 256
#define NBLK   (N_MAX / 256)   // 391
#define E_MAX  655360

// ---------------- scratch ----------------
__device__ __align__(16) __half g_XWh[(size_t)N_MAX * NCOLS];  // [node][512] fp16
__device__ __align__(16) __half g_Xh[(size_t)N_MAX * D_IN];    // fp16 X
#define BT_STRIDE 136
__device__ __align__(16) __half g_Bt[NBASES][128 * BT_STRIDE];
// sort scratch
__device__ int    g_hist[N_MAX];
__device__ int    g_rowptr[N_MAX + 1];
__device__ int    g_cursor[N_MAX];
__device__ int    g_bsum[NBLK];
__device__ int    g_dst_s[E_MAX];
__device__ float4 g_c_s[E_MAX];

// ---------------- helpers ----------------
static __device__ __forceinline__ uint32_t smem_u32(const void* p) {
    uint32_t a;
    asm("{ .reg .u64 t; cvta.to.shared.u64 t, %1; cvt.u32.u64 %0, t; }" : "=r"(a) : "l"(p));
    return a;
}
#define LDSM4(r, addr) \
    asm volatile("ldmatrix.sync.aligned.m8n8.x4.shared.b16 {%0,%1,%2,%3}, [%4];" \
        : "=r"((r)[0]), "=r"((r)[1]), "=r"((r)[2]), "=r"((r)[3]) : "r"(addr))
#define MMA_F16(c, a, b0, b1) \
    asm volatile("mma.sync.aligned.m16n8k16.row.col.f32.f16.f16.f32 " \
        "{%0,%1,%2,%3}, {%4,%5,%6,%7}, {%8,%9}, {%0,%1,%2,%3};" \
        : "+f"((c)[0]), "+f"((c)[1]), "+f"((c)[2]), "+f"((c)[3]) \
        : "r"((a)[0]), "r"((a)[1]), "r"((a)[2]), "r"((a)[3]), "r"(b0), "r"(b1))

static __device__ __forceinline__ uint32_t packh(__half a, __half b) {
    return ((uint32_t)__half_as_ushort(b) << 16) | (uint32_t)__half_as_ushort(a);
}

// ---------------- prep: X -> fp16 ----------------
__global__ void convert_x_kernel(const float* __restrict__ X, int total4) {
    int i = blockIdx.x * blockDim.x + threadIdx.x;
    if (i >= total4) return;
    float4 v = reinterpret_cast<const float4*>(X)[i];
    reinterpret_cast<uint2*>(g_Xh)[i] =
        make_uint2(packh(__float2half_rn(v.x), __float2half_rn(v.y)),
                   packh(__float2half_rn(v.z), __float2half_rn(v.w)));
}

// ---------------- prep: w_bases -> transposed fp16 smem image ----------------
__global__ void prep_b_kernel(const float* __restrict__ w_bases) {
    const int id = blockIdx.x * 256 + threadIdx.x;   // 0..65535
    const int n = id & 127, k = (id >> 7) & 127, b = id >> 14;
    g_Bt[b][n * BT_STRIDE + k] = __float2half_rn(w_bases[id]);
}

// ---------------- Phase 1: fp16 single-pass mma.sync GEMM ----------------
#define AS_STRIDE 272
#define SM_A    0
#define SM_B    34816
#define SM_TOTAL 69632

__global__ void __launch_bounds__(256, 2)
gemm_mma_kernel(int n_rows)
{
    extern __shared__ char smem[];
    const uint32_t sb = smem_u32(smem);
    const int tid = threadIdx.x, wid = tid >> 5, lane = tid & 31;
    const int base = blockIdx.x;
    const int m0 = blockIdx.y * 128;

    // A: linear copy (rows of 256B) into 272B-stride smem rows.
    for (int i = tid; i < 2048; i += 256) {
        const int row = i >> 4, seg = (i & 15) * 16;
        const size_t gsrc = (size_t)(m0 + row) * 256 + seg;
        uint4 hv = *reinterpret_cast<const uint4*>(reinterpret_cast<const char*>(g_Xh) + gsrc);
        *reinterpret_cast<uint4*>(smem + SM_A + row * AS_STRIDE + seg) = hv;
    }
    // B: straight copy (pre-built image already has 272B row stride).
    {
        const uint4* src = reinterpret_cast<const uint4*>(g_Bt[base]);
        uint4* dst = reinterpret_cast<uint4*>(smem + SM_B);
        for (int i = tid; i < 2176; i += 256) dst[i] = src[i];
    }
    __syncthreads();

    const int warp_m = (wid & 3) * 32;
    const int warp_n = (wid >> 2) * 64;

    float acc[2][8][4];
    #pragma unroll
    for (int mt = 0; mt < 2; ++mt)
        #pragma unroll
        for (int nt = 0; nt < 8; ++nt)
            #pragma unroll
            for (int i = 0; i < 4; ++i) acc[mt][nt][i] = 0.f;

    const uint32_t a_off = (uint32_t)(warp_m + (lane & 15)) * AS_STRIDE + (lane >> 4) * 16;
    const uint32_t b_off = (uint32_t)(warp_n + ((lane >> 4) << 3) + (lane & 7)) * AS_STRIDE
                         + ((lane >> 3) & 1) * 16;

    #pragma unroll
    for (int ks = 0; ks < 8; ++ks) {
        const uint32_t kb = (uint32_t)ks * 32;
        uint32_t ah[2][4];
        #pragma unroll
        for (int mt = 0; mt < 2; ++mt)
            LDSM4(ah[mt], sb + SM_A + a_off + (uint32_t)mt * 16 * AS_STRIDE + kb);
        #pragma unroll
        for (int j = 0; j < 4; ++j) {
            uint32_t b[4];
            LDSM4(b, sb + SM_B + b_off + (uint32_t)j * 16 * AS_STRIDE + kb);
            #pragma unroll
            for (int mt = 0; mt < 2; ++mt) {
                MMA_F16(acc[mt][2 * j + 0], ah[mt], b[0], b[1]);
                MMA_F16(acc[mt][2 * j + 1], ah[mt], b[2], b[3]);
            }
        }
    }

    // epilogue: fp16 XW (rows >= n_rows written but never consumed)
    const int r_base = m0 + warp_m + (lane >> 2);
    #pragma unroll
    for (int mt = 0; mt < 2; ++mt) {
        const int row0 = r_base + mt * 16;
        #pragma unroll
        for (int nt = 0; nt < 8; ++nt) {
            const int col = base * 128 + warp_n + nt * 8 + (lane & 3) * 2;
            *reinterpret_cast<__half2*>(g_XWh + (size_t)row0 * NCOLS + col) =
                __floats2half2_rn(acc[mt][nt][0], acc[mt][nt][1]);
            *reinterpret_cast<__half2*>(g_XWh + (size_t)(row0 + 8) * NCOLS + col) =
                __floats2half2_rn(acc[mt][nt][2], acc[mt][nt][3]);
        }
    }
}

// ---------------- counting sort by src ----------------
__global__ void zero_hist_kernel() {
    int i = blockIdx.x * 256 + threadIdx.x;
    if (i < N_MAX) g_hist[i] = 0;
}
__global__ void hist_kernel(const int* __restrict__ esrc, int E) {
    int e = blockIdx.x * 256 + threadIdx.x;
    if (e < E) atomicAdd(&g_hist[esrc[e]], 1);
}
__global__ void scan1_kernel() {
    __shared__ int s_w[8];
    const int t = threadIdx.x, w = t >> 5, lane = t & 31;
    const int i = blockIdx.x * 256 + t;
    const int x = g_hist[i];
    int v = x;
    #pragma unroll
    for (int o = 1; o < 32; o <<= 1) {
        int y = __shfl_up_sync(0xFFFFFFFF, v, o);
        if (lane >= o) v += y;
    }
    if (lane == 31) s_w[w] = v;
    __syncthreads();
    if (t < 8) {
        int sv = s_w[t];
        #pragma unroll
        for (int o = 1; o < 8; o <<= 1) {
            int y = __shfl_up_sync(0xFF, sv, o);
            if (t >= o) sv += y;
        }
        s_w[t] = sv;
    }
    __syncthreads();
    const int off = (w > 0) ? s_w[w - 1] : 0;
    g_rowptr[i] = off + v - x;
    if (t == 0) g_bsum[blockIdx.x] = s_w[7];
}
__global__ void scan2_kernel() {
    __shared__ int sm[512];
    const int t = threadIdx.x;
    const int v = (t < NBLK) ? g_bsum[t] : 0;
    sm[t] = v;
    __syncthreads();
    for (int o = 1; o < 512; o <<= 1) {
        int y = (t >= o) ? sm[t - o] : 0;
        __syncthreads();
        sm[t] += y;
        __syncthreads();
    }
    if (t < NBLK) g_bsum[t] = sm[t] - v;
}
__global__ void scan3_kernel(int E) {
    const int i = blockIdx.x * 256 + threadIdx.x;
    if (i < N_MAX) {
        const int r = g_rowptr[i] + g_bsum[i >> 8];
        g_rowptr[i] = r;
        g_cursor[i] = r;
    }
    if (i == 0) g_rowptr[N_MAX] = E;
}
__global__ void perm_kernel(const int* __restrict__ esrc, const int* __restrict__ edst,
                            const int* __restrict__ erel, const float* __restrict__ eval,
                            const float* __restrict__ w_rel, int E) {
    const int e = blockIdx.x * 256 + threadIdx.x;
    if (e >= E) return;
    const int s = esrc[e];
    const int pos = atomicAdd(&g_cursor[s], 1);
    g_dst_s[pos] = edst[e];
    const int r = erel[e];
    const float v = eval[e];
    float4 c;
    c.x = v * __ldg(w_rel + r * NBASES + 0);
    c.y = v * __ldg(w_rel + r * NBASES + 1);
    c.z = v * __ldg(w_rel + r * NBASES + 2);
    c.w = v * __ldg(w_rel + r * NBASES + 3);
    g_c_s[pos] = c;
}

// ---------------- Phase 2: zero output ----------------
__global__ void zero_kernel(float4* __restrict__ out, int n4) {
    int i = blockIdx.x * blockDim.x + threadIdx.x;
    if (i < n4) out[i] = make_float4(0.f, 0.f, 0.f, 0.f);
}

// ---------------- Phase 3: warp-per-src scatter (fp16 XW) ----------------
__global__ void __launch_bounds__(256)
scatter_kernel(float* __restrict__ out)
{
    const int src  = (blockIdx.x * 256 + threadIdx.x) >> 5;
    const int lane = threadIdx.x & 31;
    if (src >= N_MAX) return;
    const int beg = __ldg(g_rowptr + src);
    const int end = __ldg(g_rowptr + src + 1);
    if (beg >= end) return;

    // lane covers output cols lane*4..lane*4+3 across 4 bases
    const uint2* p = reinterpret_cast<const uint2*>(g_XWh + (size_t)src * NCOLS) + lane;
    float a[NBASES][4];
    #pragma unroll
    for (int b = 0; b < NBASES; ++b) {
        const uint2 v = __ldg(p + b * 32);
        const float2 lo = __half22float2(*reinterpret_cast<const __half2*>(&v.x));
        const float2 hi = __half22float2(*reinterpret_cast<const __half2*>(&v.y));
        a[b][0] = lo.x; a[b][1] = lo.y; a[b][2] = hi.x; a[b][3] = hi.y;
    }

    for (int j = beg; j < end; ++j) {
        const float4 c = __ldg(g_c_s + j);
        const int d = __ldg(g_dst_s + j);
        float4 acc;
        acc.x = fmaf(c.x, a[0][0], fmaf(c.y, a[1][0], fmaf(c.z, a[2][0], c.w * a[3][0])));
        acc.y = fmaf(c.x, a[0][1], fmaf(c.y, a[1][1], fmaf(c.z, a[2][1], c.w * a[3][1])));
        acc.z = fmaf(c.x, a[0][2], fmaf(c.y, a[1][2], fmaf(c.z, a[2][2], c.w * a[3][2])));
        acc.w = fmaf(c.x, a[0][3], fmaf(c.y, a[1][3], fmaf(c.z, a[2][3], c.w * a[3][3])));
        float* q = out + (size_t)d * D_OUT + lane * 4;
        asm volatile("red.global.add.v4.f32 [%0], {%1, %2, %3, %4};"
                     :: "l"(q), "f"(acc.x), "f"(acc.y), "f"(acc.z), "f"(acc.w)
                     : "memory");
    }
}

// ---------------- launch ----------------
extern "C" void kernel_launch(void* const* d_in, const int* in_sizes, int n_in,
                              void* d_out, int out_size)
{
    const float* X       = (const float*)d_in[0];
    const int*   esrc    = (const int*)  d_in[1];
    const int*   edst    = (const int*)  d_in[2];
    const int*   erel    = (const int*)  d_in[3];
    const float* eval    = (const float*)d_in[4];
    const float* w_bases = (const float*)d_in[5];
    const float* w_rel   = (const float*)d_in[6];
    float*       out     = (float*)d_out;

    const int n = in_sizes[0] / D_IN;   // 100000
    const int E = in_sizes[1];          // 640000

    cudaFuncSetAttribute(gemm_mma_kernel, cudaFuncAttributeMaxDynamicSharedMemorySize, SM_TOTAL);

    // sort pipeline
    zero_hist_kernel<<<NBLK, 256>>>();
    hist_kernel<<<(E + 255) / 256, 256>>>(esrc, E);
    scan1_kernel<<<NBLK, 256>>>();
    scan2_kernel<<<1, 512>>>();
    scan3_kernel<<<NBLK, 256>>>(E);
    perm_kernel<<<(E + 255) / 256, 256>>>(esrc, edst, erel, eval, w_rel, E);

    // GEMM prep + GEMM
    const int total4 = n * D_IN / 4;
    convert_x_kernel<<<(total4 + 255) / 256, 256>>>(X, total4);
    prep_b_kernel<<<256, 256>>>(w_bases);
    dim3 g1(NBASES, (n + 127) / 128);
    gemm_mma_kernel<<<g1, 256, SM_TOTAL>>>(n);

    // zero + scatter
    const int n4 = out_size / 4;
    zero_kernel<<<(n4 + 255) / 256, 256>>>((float4*)d_out, n4);
    scatter_kernel<<<N_MAX / 8, 256>>>(out);
}